// round 4
// baseline (speedup 1.0000x reference)
#include <cuda_runtime.h>

// ---------------------------------------------------------------------------
// TypeGAT HICS, inverted formulation, v4 — single fused kernel.
//
//  Phase A: each block builds a private SMEM hash (node -> entity) from
//           entity_index, grid-strides the edges with int4 loads, and on a
//           hit pushes packed (time,edge) keys PLUS the edge type into
//           per-entity buffers (type stored alongside key so the agg phase
//           needs no dependent gather).
//  Barrier: device-wide epoch barrier (monotonic counter — graph-replay safe).
//  Phase B: 2 entities per block; warp-parallel exact top-k (rank-by-shfl,
//           lane writes its OWN type at its rank) + masked mean over
//           query_weight rows. Counters reset to zero after consumption.
//
// Key packing preserves lax.top_k ordering: time desc, edge index asc.
// ---------------------------------------------------------------------------

#define MAX_B       4096
#define CAP         1024
#define MAX_NODES   (1 << 20)
#define MAXK        32
#define HASH_SLOTS  4096
#define HASH_MASK   (HASH_SLOTS - 1)
#define EMPTY       0xFFFFFFFFu
#define NBLK        256
#define NTHR        256

__device__ int                g_cnt_inc[MAX_B];   // zero at module load;
__device__ int                g_cnt_out[MAX_B];   // phase B restores zero.
__device__ unsigned long long g_buf_inc[(size_t)MAX_B * CAP];
__device__ unsigned long long g_buf_out[(size_t)MAX_B * CAP];
__device__ int                g_typ_inc[(size_t)MAX_B * CAP];
__device__ int                g_typ_out[(size_t)MAX_B * CAP];
__device__ unsigned long long g_bar;              // monotonic epoch barrier

__device__ __forceinline__ unsigned int hash_node(unsigned int node) {
    return (node * 2654435761u) >> 20;   // top 12 bits -> [0, 4096)
}

// Orderable key: (monotone float bits << 32) | ~edge_index.
// Max key == (largest time, smallest index) — matches lax.top_k tie-break.
__device__ __forceinline__ unsigned long long pack_key(float t, unsigned int e) {
    unsigned int tb = __float_as_uint(t);
    tb = (tb & 0x80000000u) ? ~tb : (tb | 0x80000000u);
    return ((unsigned long long)tb << 32) | (unsigned long long)(~e);
}

__device__ __forceinline__ bool probe_any(const unsigned int* s_tab, unsigned int node) {
    if (node >= (unsigned int)MAX_NODES) return false;
    unsigned int h = hash_node(node), v;
    while ((v = s_tab[h]) != EMPTY) {
        if ((v >> 12) == node) return true;
        h = (h + 1) & HASH_MASK;
    }
    return false;
}

__device__ __forceinline__ void probe_push(const unsigned int* s_tab, unsigned int node,
                                           unsigned long long key, int etype,
                                           int* __restrict__ cnt,
                                           unsigned long long* __restrict__ buf,
                                           int* __restrict__ tbuf) {
    unsigned int h = hash_node(node), v;
    while ((v = s_tab[h]) != EMPTY) {
        if ((v >> 12) == node) {
            int b = (int)(v & 0xFFFu);
            int p = atomicAdd(&cnt[b], 1);
            if (p < CAP) {
                buf[(size_t)b * CAP + p]  = key;
                tbuf[(size_t)b * CAP + p] = etype;
            }
        }
        h = (h + 1) & HASH_MASK;
    }
}

// Warp-parallel exact top-`take`. Each lane owns one candidate (key + type),
// computes its rank among the warp's keys, and writes its OWN type at that
// rank. Tie-free (distinct packed keys).
__device__ __forceinline__ void warp_select(const unsigned long long* __restrict__ buf,
                                            const int* __restrict__ tbuf,
                                            int n, int take,
                                            const int* __restrict__ etypes,
                                            int* s_types, int off, int lane) {
    if (take <= 0) return;
    if (n <= 32) {
        unsigned long long key = (lane < n) ? buf[lane]  : 0ull;
        int               typ = (lane < n) ? tbuf[lane] : 0;
        int rank = 0;
#pragma unroll
        for (int j = 0; j < 32; ++j) {
            unsigned long long o = __shfl_sync(0xffffffffu, key, j);
            rank += (o > key);
        }
        if (lane < n && rank < take)
            s_types[off + rank] = typ;
    } else {
        unsigned long long thresh = ~0ull;
        for (int r = 0; r < take; ++r) {
            unsigned long long best = 0ull;
            for (int i = lane; i < n; i += 32) {
                unsigned long long key = buf[i];
                if (key < thresh && key > best) best = key;
            }
#pragma unroll
            for (int o = 16; o; o >>= 1) {
                unsigned long long v = __shfl_xor_sync(0xffffffffu, best, o);
                if (v > best) best = v;
            }
            if (lane == 0) s_types[off + r] = etypes[~(unsigned int)best];
            thresh = best;
        }
    }
}

// ---------------------------------------------------------------------------
// Fused kernel.
// ---------------------------------------------------------------------------
__global__ void __launch_bounds__(NTHR, 2)
k_fused(const int* __restrict__ ent, const int* __restrict__ src,
        const int* __restrict__ dst, const int* __restrict__ etypes,
        const float* __restrict__ times, const float* __restrict__ qw,
        float* __restrict__ out, int B, int E, int D,
        const int* __restrict__ k_ptr, const int* __restrict__ nn_ptr) {
    __shared__ unsigned int s_tab[HASH_SLOTS];
    __shared__ int s_types[2][3 * MAXK];
    __shared__ int s_n[2];

    // ---------------- Phase A: build hash + scan edges ----------------
    for (int i = threadIdx.x; i < HASH_SLOTS; i += blockDim.x) s_tab[i] = EMPTY;
    __syncthreads();

    int nn = nn_ptr[0];
    if (nn > MAX_NODES) nn = MAX_NODES;
    for (int b = threadIdx.x; b < B && b < MAX_B; b += blockDim.x) {
        int node = ent[b];
        if (node >= 0 && node < nn) {
            unsigned int val = ((unsigned int)node << 12) | (unsigned int)b;
            unsigned int h = hash_node((unsigned int)node);
            while (atomicCAS(&s_tab[h], EMPTY, val) != EMPTY) h = (h + 1) & HASH_MASK;
        }
    }
    __syncthreads();

    {
        int tid    = blockIdx.x * blockDim.x + threadIdx.x;
        int stride = gridDim.x * blockDim.x;
        int E4     = E >> 2;
        const int4* src4 = (const int4*)src;
        const int4* dst4 = (const int4*)dst;

        for (int i = tid; i < E4; i += stride) {
            int4 d4 = dst4[i];
            int4 s4 = src4[i];
            int e0 = i << 2;
#pragma unroll
            for (int j = 0; j < 4; ++j) {
                unsigned int d = (unsigned int)((j == 0) ? d4.x : (j == 1) ? d4.y : (j == 2) ? d4.z : d4.w);
                unsigned int s = (unsigned int)((j == 0) ? s4.x : (j == 1) ? s4.y : (j == 2) ? s4.z : s4.w);
                bool hd = probe_any(s_tab, d);
                bool hs = probe_any(s_tab, s);
                if (hd | hs) {
                    int e = e0 + j;
                    unsigned long long key = pack_key(times[e], (unsigned int)e);
                    int ty = etypes[e];
                    if (hd) probe_push(s_tab, d, key, ty, g_cnt_inc, g_buf_inc, g_typ_inc);
                    if (hs) probe_push(s_tab, s, key, ty, g_cnt_out, g_buf_out, g_typ_out);
                }
            }
        }
        for (int e = (E4 << 2) + tid; e < E; e += stride) {
            unsigned int d = (unsigned int)dst[e];
            unsigned int s = (unsigned int)src[e];
            bool hd = probe_any(s_tab, d);
            bool hs = probe_any(s_tab, s);
            if (hd | hs) {
                unsigned long long key = pack_key(times[e], (unsigned int)e);
                int ty = etypes[e];
                if (hd) probe_push(s_tab, d, key, ty, g_cnt_inc, g_buf_inc, g_typ_inc);
                if (hs) probe_push(s_tab, s, key, ty, g_cnt_out, g_buf_out, g_typ_out);
            }
        }
    }

    // ---------------- Device-wide epoch barrier (replay-safe) ----------------
    __syncthreads();
    if (threadIdx.x == 0) {
        __threadfence();
        unsigned long long G   = (unsigned long long)gridDim.x;
        unsigned long long old = atomicAdd(&g_bar, 1ull);
        unsigned long long tgt = (old / G + 1ull) * G;
        while (atomicAdd(&g_bar, 0ull) < tgt) __nanosleep(64);
        __threadfence();
    }
    __syncthreads();

    // ---------------- Phase B: selection + aggregation (2 entities/block) ----
    int g       = threadIdx.x >> 7;          // group 0/1 (128 threads each)
    int gtid    = threadIdx.x & 127;
    int gwid    = gtid >> 5;
    int lane    = gtid & 31;
    int ngroups = gridDim.x * 2;

    for (int b = blockIdx.x * 2 + g; b < B && b < MAX_B; b += ngroups) {
        if (gwid < 2) {
            int k = k_ptr[0];
            if (k > MAXK) k = MAXK;
            if (k < 0)    k = 0;
            int kh = k >> 1;

            int cin  = g_cnt_inc[b];
            int cout = g_cnt_out[b];
            int nInc = cin  < CAP ? cin  : CAP;
            int nOut = cout < CAP ? cout : CAP;

            int inc_take  = kh < cin ? kh : cin;
            int remaining = (inc_take > 0) ? (k - inc_take) : k;
            int out_take  = remaining < cout ? remaining : cout;

            if (gwid == 0) {
                warp_select(&g_buf_inc[(size_t)b * CAP], &g_typ_inc[(size_t)b * CAP],
                            nInc, inc_take, etypes, s_types[g], 0, lane);
                if (lane == 0) {
                    s_n[g] = inc_take + out_take;
                    g_cnt_inc[b] = 0;           // restore invariant
                    g_cnt_out[b] = 0;
                }
            } else {
                warp_select(&g_buf_out[(size_t)b * CAP], &g_typ_out[(size_t)b * CAP],
                            nOut, out_take, etypes, s_types[g], inc_take, lane);
            }
        }
        __syncthreads();

        int n = s_n[g];
        float denom = fmaxf((float)n, 1.0f);
        for (int d = gtid; d < D; d += 128) {
            float sum = 0.0f;
            for (int i = 0; i < n; ++i)
                sum += qw[(size_t)s_types[g][i] * D + d];
            out[(size_t)b * D + d] = sum / denom;
        }
        __syncthreads();
    }
}

// ---------------------------------------------------------------------------
// Host launcher (graph-capturable: single launch).
// Inputs: entity_index, edge_src, edge_dst, edge_types, edge_times,
//         query_weight, k, num_nodes.
// ---------------------------------------------------------------------------
extern "C" void kernel_launch(void* const* d_in, const int* in_sizes, int n_in,
                              void* d_out, int out_size) {
    const int*   ent = (const int*)d_in[0];
    const int*   src = (const int*)d_in[1];
    const int*   dst = (const int*)d_in[2];
    const int*   typ = (const int*)d_in[3];
    const float* tim = (const float*)d_in[4];
    const float* qw  = (const float*)d_in[5];
    const int*   kp  = (const int*)d_in[6];
    const int*   nnp = (const int*)d_in[7];

    int B = in_sizes[0];
    int E = in_sizes[1];
    int D = (B > 0) ? (out_size / B) : 0;

    k_fused<<<NBLK, NTHR>>>(ent, src, dst, typ, tim, qw,
                            (float*)d_out, B, E, D, kp, nnp);
}

// round 5
// speedup vs baseline: 1.2262x; 1.2262x over previous
#include <cuda_runtime.h>

// ---------------------------------------------------------------------------
// TypeGAT HICS, inverted formulation, v5 — two kernels + PDL overlap.
//
//  k_scan : per-block SMEM hash (node -> entity) built from entity_index;
//           grid-stride int4 pass over edges; hits push packed (time,edge)
//           keys AND the edge type into per-entity buffers.
//  k_agg  : launched with programmatic stream serialization (PDL). Prologue
//           reads only harness inputs, then cudaGridDependencySynchronize().
//           Speculative parallel loads (cnt || key || type) collapse the
//           selection to one memory round; warp rank-by-shfl top-k; masked
//           mean over query_weight rows. Counters restored to zero.
//
// Key packing preserves lax.top_k ordering: time desc, edge index asc.
// ---------------------------------------------------------------------------

#define MAX_B       4096
#define CAP         1024
#define MAX_NODES   (1 << 20)
#define MAXK        32
#define HASH_SLOTS  4096
#define HASH_MASK   (HASH_SLOTS - 1)
#define EMPTY       0xFFFFFFFFu

__device__ int                g_cnt_inc[MAX_B];   // zero at module load;
__device__ int                g_cnt_out[MAX_B];   // k_agg restores zero.
__device__ unsigned long long g_buf_inc[(size_t)MAX_B * CAP];
__device__ unsigned long long g_buf_out[(size_t)MAX_B * CAP];
__device__ int                g_typ_inc[(size_t)MAX_B * CAP];
__device__ int                g_typ_out[(size_t)MAX_B * CAP];

__device__ __forceinline__ unsigned int hash_node(unsigned int node) {
    return (node * 2654435761u) >> 20;   // top 12 bits -> [0, 4096)
}

// Orderable key: (monotone float bits << 32) | ~edge_index.
// Max key == (largest time, smallest index) — matches lax.top_k tie-break.
// Valid keys are nonzero (sign-flip bit set for any finite time >= 0).
__device__ __forceinline__ unsigned long long pack_key(float t, unsigned int e) {
    unsigned int tb = __float_as_uint(t);
    tb = (tb & 0x80000000u) ? ~tb : (tb | 0x80000000u);
    return ((unsigned long long)tb << 32) | (unsigned long long)(~e);
}

__device__ __forceinline__ bool probe_any(const unsigned int* s_tab, unsigned int node) {
    if (node >= (unsigned int)MAX_NODES) return false;
    unsigned int h = hash_node(node), v;
    while ((v = s_tab[h]) != EMPTY) {
        if ((v >> 12) == node) return true;
        h = (h + 1) & HASH_MASK;
    }
    return false;
}

__device__ __forceinline__ void probe_push(const unsigned int* s_tab, unsigned int node,
                                           unsigned long long key, int etype,
                                           int* __restrict__ cnt,
                                           unsigned long long* __restrict__ buf,
                                           int* __restrict__ tbuf) {
    unsigned int h = hash_node(node), v;
    while ((v = s_tab[h]) != EMPTY) {
        if ((v >> 12) == node) {
            int b = (int)(v & 0xFFFu);
            int p = atomicAdd(&cnt[b], 1);
            if (p < CAP) {
                buf[(size_t)b * CAP + p]  = key;
                tbuf[(size_t)b * CAP + p] = etype;
            }
        }
        h = (h + 1) & HASH_MASK;
    }
}

// ---------------------------------------------------------------------------
// Kernel 1: edge scan with per-block SMEM hash.
// ---------------------------------------------------------------------------
__global__ void k_scan(const int* __restrict__ src, const int* __restrict__ dst,
                       const int* __restrict__ etypes,
                       const float* __restrict__ times, int E,
                       const int* __restrict__ ent, int B,
                       const int* __restrict__ nn_ptr) {
    __shared__ unsigned int s_tab[HASH_SLOTS];
    for (int i = threadIdx.x; i < HASH_SLOTS; i += blockDim.x) s_tab[i] = EMPTY;
    __syncthreads();

    int nn = nn_ptr[0];
    if (nn > MAX_NODES) nn = MAX_NODES;
    for (int b = threadIdx.x; b < B && b < MAX_B; b += blockDim.x) {
        int node = ent[b];
        if (node >= 0 && node < nn) {
            unsigned int val = ((unsigned int)node << 12) | (unsigned int)b;
            unsigned int h = hash_node((unsigned int)node);
            while (atomicCAS(&s_tab[h], EMPTY, val) != EMPTY) h = (h + 1) & HASH_MASK;
        }
    }
    __syncthreads();

    int tid    = blockIdx.x * blockDim.x + threadIdx.x;
    int stride = gridDim.x * blockDim.x;
    int E4     = E >> 2;
    const int4* src4 = (const int4*)src;
    const int4* dst4 = (const int4*)dst;

    for (int i = tid; i < E4; i += stride) {
        int4 d4 = dst4[i];
        int4 s4 = src4[i];
        int e0 = i << 2;
#pragma unroll
        for (int j = 0; j < 4; ++j) {
            unsigned int d = (unsigned int)((j == 0) ? d4.x : (j == 1) ? d4.y : (j == 2) ? d4.z : d4.w);
            unsigned int s = (unsigned int)((j == 0) ? s4.x : (j == 1) ? s4.y : (j == 2) ? s4.z : s4.w);
            bool hd = probe_any(s_tab, d);
            bool hs = probe_any(s_tab, s);
            if (hd | hs) {
                int e = e0 + j;
                unsigned long long key = pack_key(times[e], (unsigned int)e);
                int ty = etypes[e];
                if (hd) probe_push(s_tab, d, key, ty, g_cnt_inc, g_buf_inc, g_typ_inc);
                if (hs) probe_push(s_tab, s, key, ty, g_cnt_out, g_buf_out, g_typ_out);
            }
        }
    }
    for (int e = (E4 << 2) + tid; e < E; e += stride) {
        unsigned int d = (unsigned int)dst[e];
        unsigned int s = (unsigned int)src[e];
        bool hd = probe_any(s_tab, d);
        bool hs = probe_any(s_tab, s);
        if (hd | hs) {
            unsigned long long key = pack_key(times[e], (unsigned int)e);
            int ty = etypes[e];
            if (hd) probe_push(s_tab, d, key, ty, g_cnt_inc, g_buf_inc, g_typ_inc);
            if (hs) probe_push(s_tab, s, key, ty, g_cnt_out, g_buf_out, g_typ_out);
        }
    }
}

// Warp-parallel exact top-`take`. Candidate key+type were loaded
// speculatively by the caller (one memory round). Tie-free keys.
__device__ __forceinline__ void warp_select_reg(unsigned long long keyraw, int typraw,
                                                const unsigned long long* __restrict__ buf,
                                                const int* __restrict__ etypes,
                                                int n, int take,
                                                int* s_types, int off, int lane) {
    if (take <= 0) return;
    if (n <= 32) {
        unsigned long long key = (lane < n) ? keyraw : 0ull;
        int rank = 0;
#pragma unroll
        for (int j = 0; j < 32; ++j) {
            unsigned long long o = __shfl_sync(0xffffffffu, key, j);
            rank += (o > key);
        }
        if (lane < n && rank < take)
            s_types[off + rank] = typraw;
    } else {
        unsigned long long thresh = ~0ull;
        for (int r = 0; r < take; ++r) {
            unsigned long long best = 0ull;
            for (int i = lane; i < n; i += 32) {
                unsigned long long key = buf[i];
                if (key < thresh && key > best) best = key;
            }
#pragma unroll
            for (int o = 16; o; o >>= 1) {
                unsigned long long v = __shfl_xor_sync(0xffffffffu, best, o);
                if (v > best) best = v;
            }
            if (lane == 0) s_types[off + r] = etypes[~(unsigned int)best];
            thresh = best;
        }
    }
}

// ---------------------------------------------------------------------------
// Kernel 2: selection + masked mean. PDL-aware.
// ---------------------------------------------------------------------------
__global__ void k_agg(const int* __restrict__ etypes, const float* __restrict__ qw,
                      float* __restrict__ out, int B, int D,
                      const int* __restrict__ k_ptr) {
    int b = blockIdx.x;
    if (b >= B) return;

    __shared__ int s_types[3 * MAXK];
    __shared__ int s_n;

    int tid = threadIdx.x, wid = tid >> 5, lane = tid & 31;

    // Prologue: harness inputs only (not written by k_scan).
    int k = k_ptr[0];
    if (k > MAXK) k = MAXK;
    if (k < 0)    k = 0;
    int kh = k >> 1;

    // Wait for k_scan's results to be visible.
    cudaGridDependencySynchronize();

    if (wid < 2) {
        const unsigned long long* buf  = (wid == 0) ? &g_buf_inc[(size_t)b * CAP]
                                                    : &g_buf_out[(size_t)b * CAP];
        const int*                tbuf = (wid == 0) ? &g_typ_inc[(size_t)b * CAP]
                                                    : &g_typ_out[(size_t)b * CAP];
        // Speculative loads — issue in parallel with the counter loads.
        unsigned long long keyraw = buf[lane];
        int                typraw = tbuf[lane];
        int cin  = g_cnt_inc[b];
        int cout = g_cnt_out[b];

        int nInc = cin  < CAP ? cin  : CAP;
        int nOut = cout < CAP ? cout : CAP;
        int inc_take  = kh < cin ? kh : cin;
        int remaining = (inc_take > 0) ? (k - inc_take) : k;
        int out_take  = remaining < cout ? remaining : cout;

        if (wid == 0) {
            warp_select_reg(keyraw, typraw, buf, etypes, nInc, inc_take,
                            s_types, 0, lane);
            if (lane == 0) {
                s_n = inc_take + out_take;
                g_cnt_inc[b] = 0;       // restore module-load invariant
                g_cnt_out[b] = 0;
            }
        } else {
            warp_select_reg(keyraw, typraw, buf, etypes, nOut, out_take,
                            s_types, inc_take, lane);
        }
    }
    __syncthreads();

    int n = s_n;
    float denom = fmaxf((float)n, 1.0f);
    for (int d = tid; d < D; d += blockDim.x) {
        float sum = 0.0f;
        for (int i = 0; i < n; ++i)
            sum += qw[(size_t)s_types[i] * D + d];
        out[(size_t)b * D + d] = sum / denom;
    }
}

// ---------------------------------------------------------------------------
// Host launcher (graph-capturable: launches only; PDL edge between them).
// Inputs: entity_index, edge_src, edge_dst, edge_types, edge_times,
//         query_weight, k, num_nodes.
// ---------------------------------------------------------------------------
extern "C" void kernel_launch(void* const* d_in, const int* in_sizes, int n_in,
                              void* d_out, int out_size) {
    const int*   ent = (const int*)d_in[0];
    const int*   src = (const int*)d_in[1];
    const int*   dst = (const int*)d_in[2];
    const int*   typ = (const int*)d_in[3];
    const float* tim = (const float*)d_in[4];
    const float* qw  = (const float*)d_in[5];
    const int*   kp  = (const int*)d_in[6];
    const int*   nnp = (const int*)d_in[7];

    int B = in_sizes[0];
    int E = in_sizes[1];
    int D = (B > 0) ? (out_size / B) : 0;

    int nblk = (E / 4 + 255) / 256;
    if (nblk > 256) nblk = 256;
    if (nblk < 1)   nblk = 1;

    k_scan<<<nblk, 256>>>(src, dst, typ, tim, E, ent, B, nnp);

    // PDL launch: k_agg's launch latency overlaps k_scan's execution.
    cudaLaunchAttribute attrs[1];
    attrs[0].id = cudaLaunchAttributeProgrammaticStreamSerialization;
    attrs[0].val.programmaticStreamSerializationAllowed = 1;
    cudaLaunchConfig_t cfg = {};
    cfg.gridDim  = dim3((unsigned)B, 1, 1);
    cfg.blockDim = dim3(128, 1, 1);
    cfg.dynamicSmemBytes = 0;
    cfg.stream = 0;
    cfg.attrs = attrs;
    cfg.numAttrs = 1;
    cudaLaunchKernelEx(&cfg, k_agg, typ, qw, (float*)d_out, B, D, kp);
}